// round 15
// baseline (speedup 1.0000x reference)
#include <cuda_runtime.h>

// HoG layer, fused, dense-load edition.
// Phase 1 (x2 chunks): flat-indexed float4 staging of rows {8cy+6,7,8}
//   (3 channels summed, OOB zero) -> sbuf; bin one cell/thread from LDS,
//   write all 9 hist bins + per-cell ssq (no zero pass, no validity checks).
// Phase 1.5: one thread per block computes inv = 1/(sqrt(ssq)+eps) once.
// Phase 2:  warp-per-block contiguous 144B stores (R14, proven).
//   input  x: (1, 3, 4096, 4096) f32 ; output feat: (511, 511, 36) f32

#define IMG   4096
#define CELLS 512
#define OUTD  511
#define TC    16
#define HW    (TC + 1)      // 17
#define NCELL (HW * HW)     // 289
#define NT    256
#define NSEG  34            // float4 per staged row
#define SEGW  (NSEG * 4)    // 136 floats

__global__ __launch_bounds__(NT)
void hog_fused_kernel(const float* __restrict__ x, float* __restrict__ out)
{
    __shared__ __align__(16) float sbuf[27 * SEGW];   // 14688 B (chunk-reused)
    __shared__ __align__(16) float hist[NCELL * 9];   // 10404 B
    __shared__ float cssq[NCELL];                     // 1156 B
    __shared__ float binv[NT];                        // 1024 B

    const int cx0 = blockIdx.x * TC;
    const int cy0 = blockIdx.y * TC;
    const int tid = threadIdx.x;
    const long chs = (long)IMG * IMG;
    const int gcb = 8 * cx0 + 4;        // global col base of staged window

    // ---- Phase 1: two chunks of cell-rows (9 + 8) ----
    #pragma unroll
    for (int chunk = 0; chunk < 2; chunk++) {
        const int r0  = chunk ? 9 : 0;
        const int nr  = chunk ? 8 : 9;
        const int npos = nr * 3 * NSEG;          // 918 / 816 float4 positions

        // Stage: 4 positions/thread, batched 2+2 so 6 LDG.128 are in flight.
        #pragma unroll
        for (int g = 0; g < 2; g++) {
            float4 A[2], B[2], C[2];
            int soff[2];  bool pos_ok[2];
            #pragma unroll
            for (int j = 0; j < 2; j++) {
                const int i   = tid + (2 * g + j) * NT;
                const int rf  = i / NSEG;
                const int seg = i - rf * NSEG;
                const int cr  = rf / 3;          // cell-row within chunk
                const int sub = rf - 3 * cr;
                const int grow = 8 * (cy0 + r0 + cr) + 6 + sub;
                const int gcol = gcb + 4 * seg;
                pos_ok[j] = (i < npos);
                const bool data_ok = pos_ok[j] && (grow < IMG) && (gcol < IMG);
                const float4 z = make_float4(0.f, 0.f, 0.f, 0.f);
                const float* p = x + (long)grow * IMG + gcol;
                A[j] = data_ok ? *(const float4*)(p)           : z;
                B[j] = data_ok ? *(const float4*)(p + chs)     : z;
                C[j] = data_ok ? *(const float4*)(p + 2 * chs) : z;
                soff[j] = rf * SEGW + 4 * seg;
            }
            #pragma unroll
            for (int j = 0; j < 2; j++) {
                if (pos_ok[j]) {
                    float4 s;
                    s.x = A[j].x + B[j].x + C[j].x;
                    s.y = A[j].y + B[j].y + C[j].y;
                    s.z = A[j].z + B[j].z + C[j].z;
                    s.w = A[j].w + B[j].w + C[j].w;
                    *(float4*)&sbuf[soff[j]] = s;
                }
            }
        }
        __syncthreads();

        // Bin: one cell per thread; OOB staged as zero -> no checks.
        const int ncl = nr * HW;                 // 153 / 136
        if (tid < ncl) {
            const int lcyl = tid / HW;
            const int lcx  = tid - lcyl * HW;
            const float* rb = &sbuf[(3 * lcyl) * SEGW + 8 * lcx];
            const float su = rb[3];              // row 8cy+6, col px
            const float sl = rb[SEGW + 2];       // row 8cy+7, col px-1
            const float sr = rb[SEGW + 4];       // row 8cy+7, col px+1
            const float sd = rb[2 * SEGW + 3];   // row 8cy+8, col px

            const float gv = sd - su;
            const float gh = sr - sl;
            const float mag = sqrtf(gv * gv + gh * gh + 1e-6f);
            const float ang = fabsf(atanf(gh / (gv + 1e-9f)))
                              * (180.0f / 3.14159265358979323846f);

            const float t  = ang * 0.05f;            // ang / 20
            const int   ji = (int)floorf(t - 0.5f);  // in [-1, 4]
            const float vj  = mag * ((float)ji + 1.5f - t);
            const float vj1 = mag - vj;
            const int i0 = (ji < 0) ? 8 : ji;        // mod(ji, 9)
            const int i1 = ji + 1;                   // never == i0

            const int c = (r0 + lcyl) * HW + lcx;
            float* hrow = &hist[c * 9];
            #pragma unroll
            for (int b = 0; b < 9; b++)
                hrow[b] = (b == i0) ? vj : ((b == i1) ? vj1 : 0.0f);
            cssq[c] = vj * vj + vj1 * vj1;
        }
        __syncthreads();                         // sbuf reuse / hist ready
    }

    // ---- Phase 1.5: one block-inv per thread (256 div/sqrt total) ----
    {
        const int ly = tid >> 4;
        const int lx = tid & 15;
        const int cbase = ly * HW + lx;
        const float ss = cssq[cbase] + cssq[cbase + 1]
                       + cssq[cbase + HW] + cssq[cbase + HW + 1];
        binv[tid] = 1.0f / (sqrtf(ss) + 1e-9f);
    }
    __syncthreads();

    // ---- Phase 2: warp per 2 output rows, contiguous stores (R14) ----
    const int warp = tid >> 5;
    const int lane = tid & 31;

    const int s1 = lane / 9;
    const int b1 = lane - s1 * 9;
    const int off1 = ((s1 & 1) ? 9 : 0) + ((s1 & 2) ? HW * 9 : 0) + b1;
    const int off2 = HW * 9 + 9 + 5 + lane;     // comps 32..35: seg h11, bins 5..8

    const int nlx = (cx0 + TC <= OUTD) ? TC : (OUTD - cx0);   // 16 or 15

    #pragma unroll
    for (int ry = 0; ry < 2; ry++) {
        const int ly = 2 * warp + ry;
        const int oy = cy0 + ly;
        if (oy >= OUTD) continue;
        float* orow = out + ((size_t)oy * OUTD + cx0) * 36;
        const int hbase = ly * HW;
        const int bbase = ly * 16;

        #pragma unroll 2
        for (int lx = 0; lx < nlx; lx++) {
            const float inv = binv[bbase + lx];            // broadcast LDS
            const float* hb = &hist[(hbase + lx) * 9];
            const float w1 = hb[off1] * inv;
            float* ob = orow + lx * 36;
            ob[lane] = w1;
            if (lane < 4)
                ob[32 + lane] = hb[off2] * inv;
        }
    }
}

extern "C" void kernel_launch(void* const* d_in, const int* in_sizes, int n_in,
                              void* d_out, int out_size)
{
    const float* x = (const float*)d_in[0];
    float* out = (float*)d_out;
    dim3 grid(CELLS / TC, CELLS / TC);   // 32 x 32 tiles = 1024 CTAs
    hog_fused_kernel<<<grid, NT>>>(x, out);
}

// round 16
// speedup vs baseline: 1.3542x; 1.3542x over previous
#include <cuda_runtime.h>

// HoG layer, fused — R14 structure (best: 21.2us) with the register budget
// unlocked (launch_bounds min-blocks=5 -> up to 51 regs) so the 24-deep
// phase-1 load batch is truly resident instead of serialized at 32 regs.
// Phase 1:   2 cells/thread scattered gather, 24 LDGs in flight,
//            all-9-bin hist writes + per-cell ssq (no zero pass).
// Phase 1.5: one thread per block computes inv = 1/(sqrt(ssq)+eps) once.
// Phase 2:   warp-per-block contiguous 144B stores.
//   input  x: (1, 3, 4096, 4096) f32 ; output feat: (511, 511, 36) f32

#define IMG   4096
#define CELLS 512
#define OUTD  511
#define TC    16          // cells per tile side
#define HW    (TC + 1)    // 17: tile + halo
#define NCELL (HW * HW)   // 289
#define NT    256

__global__ __launch_bounds__(NT, 5)
void hog_fused_kernel(const float* __restrict__ x, float* __restrict__ out)
{
    __shared__ __align__(16) float hist[NCELL * 9];   // 10404 B
    __shared__ float cssq[NCELL];                     // 1156 B
    __shared__ float binv[NT];                        // 1024 B

    const int cx0 = blockIdx.x * TC;
    const int cy0 = blockIdx.y * TC;
    const int tid = threadIdx.x;
    const long chs = (long)IMG * IMG;

    // ---- Phase 1: two cells per thread, all 24 loads issued up front ----
    float v[2][12];
    bool  valid[2];
    const float* base[2];
    bool  hd[2], hr[2];

    #pragma unroll
    for (int it = 0; it < 2; it++) {
        const int c = tid + it * NT;
        const int lcy = c / HW;
        const int lcx = c - lcy * HW;
        const int cy = cy0 + lcy;
        const int cx = cx0 + lcx;
        valid[it] = (c < NCELL) && (cy < CELLS) && (cx < CELLS);
        const int py = cy * 8 + 7;
        const int px = cx * 8 + 7;
        base[it] = x + (long)py * IMG + px;
        hd[it] = (py + 1 < IMG);
        hr[it] = (px + 1 < IMG);
    }

    #pragma unroll
    for (int it = 0; it < 2; it++) {
        const float* p = base[it];
        const bool va = valid[it];
        const bool vd = va && hd[it];
        const bool vr = va && hr[it];
        #pragma unroll
        for (int ch = 0; ch < 3; ch++) {
            const float* pc = p + ch * chs;
            v[it][ch * 4 + 0] = va ? pc[-IMG] : 0.0f;
            v[it][ch * 4 + 1] = va ? pc[-1]   : 0.0f;
            v[it][ch * 4 + 2] = vd ? pc[IMG]  : 0.0f;
            v[it][ch * 4 + 3] = vr ? pc[1]    : 0.0f;
        }
    }

    #pragma unroll
    for (int it = 0; it < 2; it++) {
        if (!valid[it]) continue;
        const float su = v[it][0] + v[it][4] + v[it][8];
        const float sl = v[it][1] + v[it][5] + v[it][9];
        const float sd = v[it][2] + v[it][6] + v[it][10];
        const float sr = v[it][3] + v[it][7] + v[it][11];

        const float gv = sd - su;
        const float gh = sr - sl;
        const float mag = sqrtf(gv * gv + gh * gh + 1e-6f);
        const float ang = fabsf(atanf(gh / (gv + 1e-9f)))
                          * (180.0f / 3.14159265358979323846f);

        const float t  = ang * 0.05f;                 // ang / 20
        const int   ji = (int)floorf(t - 0.5f);       // in [-1, 4]
        const float vj  = mag * ((float)ji + 1.5f - t);
        const float vj1 = mag - vj;

        const int i0 = (ji < 0) ? 8 : ji;   // mod(ji, 9)
        const int i1 = ji + 1;              // never == i0
        const int c  = tid + it * NT;
        float* hrow = &hist[c * 9];
        #pragma unroll
        for (int b = 0; b < 9; b++)
            hrow[b] = (b == i0) ? vj : ((b == i1) ? vj1 : 0.0f);
        cssq[c] = vj * vj + vj1 * vj1;
    }
    __syncthreads();

    // ---- Phase 1.5: one block-inv per thread (256 div/sqrt total) ----
    {
        const int ly = tid >> 4;
        const int lx = tid & 15;
        const int cbase = ly * HW + lx;
        const float ss = cssq[cbase] + cssq[cbase + 1]
                       + cssq[cbase + HW] + cssq[cbase + HW + 1];
        binv[tid] = 1.0f / (sqrtf(ss) + 1e-9f);
    }
    __syncthreads();

    // ---- Phase 2: warp per 2 output rows, contiguous stores ----
    const int warp = tid >> 5;
    const int lane = tid & 31;

    // lane -> hist offsets: comp `lane` (0..31) and comp `32+lane` (lanes 0..3)
    const int s1 = lane / 9;
    const int b1 = lane - s1 * 9;
    const int off1 = ((s1 & 1) ? 9 : 0) + ((s1 & 2) ? HW * 9 : 0) + b1;
    const int off2 = HW * 9 + 9 + 5 + lane;   // comps 32..35: seg h11, bins 5..8

    const int nlx = (cx0 + TC <= OUTD) ? TC : (OUTD - cx0);   // 16 or 15

    #pragma unroll
    for (int ry = 0; ry < 2; ry++) {
        const int ly = 2 * warp + ry;
        const int oy = cy0 + ly;
        if (oy >= OUTD) continue;
        float* orow = out + ((size_t)oy * OUTD + cx0) * 36;
        const int hbase = ly * HW;
        const int bbase = ly * 16;

        #pragma unroll 2
        for (int lx = 0; lx < nlx; lx++) {
            const float inv = binv[bbase + lx];            // broadcast LDS
            const float* hb = &hist[(hbase + lx) * 9];
            const float w1 = hb[off1] * inv;
            float* ob = orow + lx * 36;
            ob[lane] = w1;
            if (lane < 4)
                ob[32 + lane] = hb[off2] * inv;
        }
    }
}

extern "C" void kernel_launch(void* const* d_in, const int* in_sizes, int n_in,
                              void* d_out, int out_size)
{
    const float* x = (const float*)d_in[0];
    float* out = (float*)d_out;
    dim3 grid(CELLS / TC, CELLS / TC);   // 32 x 32 tiles = 1024 CTAs
    hog_fused_kernel<<<grid, NT>>>(x, out);
}